// round 17
// baseline (speedup 1.0000x reference)
#include <cuda_runtime.h>
#include <math.h>
#include <cstdint>

constexpr int T   = 2048;
constexpr int H   = 1024;
constexpr int NH  = 16;
constexpr int NKV = 4;
constexpr int HD  = 64;
constexpr int NE  = 8;
constexpr int F   = 2048;
constexpr int QKVN = (NH + 2 * NKV) * HD;  // 1536
constexpr float EPS = 1e-5f;

// ---- tf32 helpers (attention) ---------------------------------------------
__device__ __forceinline__ unsigned f2tf(float x) {
    unsigned r; asm("cvt.rna.tf32.f32 %0, %1;" : "=r"(r) : "f"(x)); return r;
}
__device__ __forceinline__ void mma_tf32(float* c, const unsigned* a, const unsigned* b) {
    asm("mma.sync.aligned.m16n8k8.row.col.f32.tf32.tf32.f32 "
        "{%0,%1,%2,%3}, {%4,%5,%6,%7}, {%8,%9}, {%0,%1,%2,%3};"
        : "+f"(c[0]), "+f"(c[1]), "+f"(c[2]), "+f"(c[3])
        : "r"(a[0]), "r"(a[1]), "r"(a[2]), "r"(a[3]), "r"(b[0]), "r"(b[1]));
}

// ---- bf16 helpers ----------------------------------------------------------
__device__ __forceinline__ unsigned f2bf2(float lo, float hi) {
    unsigned r;
    asm("cvt.rn.bf16x2.f32 %0, %1, %2;" : "=r"(r) : "f"(hi), "f"(lo));
    return r;
}
__device__ __forceinline__ void mma_bf16(float* c, const unsigned* a, const unsigned* b) {
    asm("mma.sync.aligned.m16n8k16.row.col.f32.bf16.bf16.f32 "
        "{%0,%1,%2,%3}, {%4,%5,%6,%7}, {%8,%9}, {%0,%1,%2,%3};"
        : "+f"(c[0]), "+f"(c[1]), "+f"(c[2]), "+f"(c[3])
        : "r"(a[0]), "r"(a[1]), "r"(a[2]), "r"(a[3]), "r"(b[0]), "r"(b[1]));
}
__device__ __forceinline__ uint32_t smem_u32(const void* p) {
    uint32_t a;
    asm("{ .reg .u64 t; cvta.to.shared.u64 t, %1; cvt.u32.u64 %0, t; }"
        : "=r"(a) : "l"(p));
    return a;
}
__device__ __forceinline__ void ldsm_x4(unsigned& r0, unsigned& r1,
                                        unsigned& r2, unsigned& r3, uint32_t addr) {
    asm volatile("ldmatrix.sync.aligned.m8n8.x4.shared.b16 {%0,%1,%2,%3}, [%4];"
        : "=r"(r0), "=r"(r1), "=r"(r2), "=r"(r3) : "r"(addr));
}

// ---- scratch: device globals, referenced ONLY inside device code ----------
__device__ float g_xnorm[T * H];
__device__ float g_qkv[T * QKVN];
__device__ float g_attn[T * NH * HD];
__device__ float g_x1[T * H];
__device__ float g_xnorm2[T * H];
__device__ int   g_cnt[NE];
__device__ int   g_ptok[NE * T];
__device__ int   g_slot[2 * T];
__device__ float g_gatew[2 * T];
__device__ float g_act[NE * T * F];
__device__ float g_y[NE * T * H];
// bf16 (packed x2) weight caches, converted each launch
__device__ unsigned g_wqkv_bf[QKVN * H / 2];
__device__ unsigned g_wo_bf[H * NH * HD / 2];
__device__ unsigned g_w1_bf[NE * F * H / 2];
__device__ unsigned g_w2_bf[NE * H * F / 2];
__device__ unsigned g_w3_bf[NE * F * H / 2];

// ---------------------------------------------------------------- utilities
__device__ __forceinline__ float block_sum_256(float v) {
    __shared__ float red[8];
    #pragma unroll
    for (int o = 16; o; o >>= 1) v += __shfl_xor_sync(0xffffffffu, v, o);
    if ((threadIdx.x & 31) == 0) red[threadIdx.x >> 5] = v;
    __syncthreads();
    if (threadIdx.x == 0) {
        float s = 0.f;
        #pragma unroll
        for (int i = 0; i < 8; i++) s += red[i];
        red[0] = s;
    }
    __syncthreads();
    float r = red[0];
    __syncthreads();
    return r;
}

// ------------------------------------------------------------------ kernels
__global__ void zero_cnt_kernel() {
    if (threadIdx.x < NE) g_cnt[threadIdx.x] = 0;
}

// f32 -> packed bf16x2 (round-to-nearest, same as in-kernel path)
template <int WHICH>
__global__ __launch_bounds__(256) void cvt_bf16_kernel(const float4* __restrict__ src, int n4) {
    uint2* dst;
    if (WHICH == 0) dst = (uint2*)g_wqkv_bf;
    else if (WHICH == 1) dst = (uint2*)g_wo_bf;
    else if (WHICH == 2) dst = (uint2*)g_w1_bf;
    else if (WHICH == 3) dst = (uint2*)g_w2_bf;
    else dst = (uint2*)g_w3_bf;
    int i = blockIdx.x * 256 + threadIdx.x;
    int stride = gridDim.x * 256;
    for (; i < n4; i += stride) {
        float4 v = src[i];
        uint2 o;
        o.x = f2bf2(v.x, v.y);
        o.y = f2bf2(v.z, v.w);
        dst[i] = o;
    }
}

template <int MODE>
__global__ __launch_bounds__(256) void rmsnorm_kernel(
    const float* __restrict__ xin, const float* __restrict__ w)
{
    int t = blockIdx.x;
    const float* x = (MODE == 0) ? xin : (const float*)g_x1;
    float* out = (MODE == 0) ? g_xnorm : g_xnorm2;
    const float* xr = x + (size_t)t * H;
    float ss = 0.f;
    for (int i = threadIdx.x; i < H; i += 256) { float v = xr[i]; ss += v * v; }
    float tot = block_sum_256(ss);
    float scale = rsqrtf(tot / (float)H + EPS);
    for (int i = threadIdx.x; i < H; i += 256)
        out[(size_t)t * H + i] = xr[i] * scale * w[i];
}

// --- unified 128x128 bf16 GEMM: ldmatrix + double buffer + bf16 weights ----
// MODE 0: g_qkv  = g_xnorm * w_qkv^T                (N=QKVN, K=H)
// MODE 1: g_x1   = g_attn  * w_o^T + resid          (N=H,    K=H)
// MODE 2: g_act  = Xg      * w3^T   (gathered rows) (N=F,    K=H)
// MODE 3: g_act  = silu(Xg * w1^T) * g_act          (N=F,    K=H)
// MODE 4: g_y    = g_act   * w2^T                   (N=H,    K=F)
template <int MODE>
__global__ __launch_bounds__(256) void gemm_tc(const float* __restrict__ resid)
{
    constexpr int K = (MODE == 4) ? F : H;
    constexpr int NSLAB = K / 32;
    constexpr int BUFB = 128 * 80;   // bytes per buffer

    __shared__ __align__(16) unsigned sA[2][128][20];
    __shared__ __align__(16) unsigned sB[2][128][20];
    __shared__ int toks[128];

    int e   = (MODE >= 2) ? blockIdx.z : 0;
    int cnt = (MODE >= 2) ? g_cnt[e] : T;
    int m0  = blockIdx.y * 128;
    if (m0 >= cnt) return;
    int n0  = blockIdx.x * 128;

    int tid  = threadIdx.x;
    int warp = tid >> 5, lane = tid & 31;
    int g    = lane >> 2, tig = lane & 3;
    int wm   = warp >> 2, wn = warp & 3;
    int lr   = tid >> 1;
    int lk   = (tid & 1) * 16;   // element offset within K-slab
    int kp   = (tid & 1) * 8;    // packed offset

    if (MODE == 2 || MODE == 3) {
        if (tid < 128) {
            int s = m0 + tid;
            toks[tid] = (s < cnt) ? g_ptok[e * T + s] : g_ptok[e * T];
        }
        __syncthreads();
    }

    const float* Arow;
    if (MODE == 0)      Arow = g_xnorm + (size_t)(m0 + lr) * H;
    else if (MODE == 1) Arow = g_attn  + (size_t)(m0 + lr) * H;
    else if (MODE == 4) Arow = g_act   + (size_t)(e * T + m0 + lr) * F;
    else                Arow = g_xnorm2 + (size_t)toks[lr] * H;

    const unsigned* Wbf;
    if (MODE == 0)      Wbf = g_wqkv_bf;
    else if (MODE == 1) Wbf = g_wo_bf;
    else if (MODE == 2) Wbf = g_w3_bf;
    else if (MODE == 3) Wbf = g_w1_bf;
    else                Wbf = g_w2_bf;
    size_t estrideE = (MODE >= 2) ? (size_t)F * H : 0;   // elements (w2 same F*H)
    const unsigned* Brow = Wbf + ((size_t)e * estrideE + (size_t)(n0 + lr) * K) / 2 + kp;

    // ldmatrix lane-address offsets (bytes, within one buffer)
    uint32_t aAs = smem_u32(sA), aBs = smem_u32(sB);
    uint32_t aoff[4], boff[2];
    #pragma unroll
    for (int mt = 0; mt < 4; mt++)
        aoff[mt] = (uint32_t)((wm * 64 + mt * 16 + (lane & 15)) * 80 + ((lane >> 4) << 4));
    #pragma unroll
    for (int ntp = 0; ntp < 2; ntp++)
        boff[ntp] = (uint32_t)((wn * 32 + ntp * 16 + (lane & 7) + ((lane >> 4) << 3)) * 80
                               + (((lane >> 3) & 1) << 4));

    float acc[4][4][4];
    #pragma unroll
    for (int mt = 0; mt < 4; mt++)
        #pragma unroll
        for (int nt = 0; nt < 4; nt++)
            #pragma unroll
            for (int r = 0; r < 4; r++) acc[mt][nt][r] = 0.f;

    float4 pa[4];
    uint4  pb[2];

    // prologue: fetch + stage slab 0
    #pragma unroll
    for (int i = 0; i < 4; i++) pa[i] = *(const float4*)(Arow + lk + i * 4);
    pb[0] = *(const uint4*)(Brow);
    pb[1] = *(const uint4*)(Brow + 4);
    {
        uint4 wa0, wa1;
        wa0.x = f2bf2(pa[0].x, pa[0].y); wa0.y = f2bf2(pa[0].z, pa[0].w);
        wa0.z = f2bf2(pa[1].x, pa[1].y); wa0.w = f2bf2(pa[1].z, pa[1].w);
        wa1.x = f2bf2(pa[2].x, pa[2].y); wa1.y = f2bf2(pa[2].z, pa[2].w);
        wa1.z = f2bf2(pa[3].x, pa[3].y); wa1.w = f2bf2(pa[3].z, pa[3].w);
        *(uint4*)&sA[0][lr][kp]     = wa0;
        *(uint4*)&sA[0][lr][kp + 4] = wa1;
        *(uint4*)&sB[0][lr][kp]     = pb[0];
        *(uint4*)&sB[0][lr][kp + 4] = pb[1];
    }
    __syncthreads();

    for (int s = 0;;) {
        bool more = (s + 1 < NSLAB);
        if (more) {   // prefetch next slab into regs (overlaps MMA)
            int k0 = (s + 1) * 32;
            #pragma unroll
            for (int i = 0; i < 4; i++) pa[i] = *(const float4*)(Arow + k0 + lk + i * 4);
            pb[0] = *(const uint4*)(Brow + k0 / 2);
            pb[1] = *(const uint4*)(Brow + k0 / 2 + 4);
        }
        // MMA on current buffer
        {
            uint32_t bA = aAs + (uint32_t)(s & 1) * BUFB;
            uint32_t bB = aBs + (uint32_t)(s & 1) * BUFB;
            #pragma unroll
            for (int kk = 0; kk < 2; kk++) {
                unsigned aR[4][4], bR[4][2];
                #pragma unroll
                for (int mt = 0; mt < 4; mt++)
                    ldsm_x4(aR[mt][0], aR[mt][1], aR[mt][2], aR[mt][3],
                            bA + aoff[mt] + kk * 32);
                #pragma unroll
                for (int ntp = 0; ntp < 2; ntp++) {
                    unsigned r0, r1, r2, r3;
                    ldsm_x4(r0, r1, r2, r3, bB + boff[ntp] + kk * 32);
                    bR[2 * ntp][0] = r0;     bR[2 * ntp][1] = r1;
                    bR[2 * ntp + 1][0] = r2; bR[2 * ntp + 1][1] = r3;
                }
                #pragma unroll
                for (int mt = 0; mt < 4; mt++)
                    #pragma unroll
                    for (int nt = 0; nt < 4; nt++)
                        mma_bf16(acc[mt][nt], aR[mt], bR[nt]);
            }
        }
        if (!more) break;
        // stage next slab into the other buffer
        {
            int b = (s + 1) & 1;
            uint4 wa0, wa1;
            wa0.x = f2bf2(pa[0].x, pa[0].y); wa0.y = f2bf2(pa[0].z, pa[0].w);
            wa0.z = f2bf2(pa[1].x, pa[1].y); wa0.w = f2bf2(pa[1].z, pa[1].w);
            wa1.x = f2bf2(pa[2].x, pa[2].y); wa1.y = f2bf2(pa[2].z, pa[2].w);
            wa1.z = f2bf2(pa[3].x, pa[3].y); wa1.w = f2bf2(pa[3].z, pa[3].w);
            *(uint4*)&sA[b][lr][kp]     = wa0;
            *(uint4*)&sA[b][lr][kp + 4] = wa1;
            *(uint4*)&sB[b][lr][kp]     = pb[0];
            *(uint4*)&sB[b][lr][kp + 4] = pb[1];
        }
        __syncthreads();
        s++;
    }

    // ------------------------- epilogue (fragment layout) ------------------
    #pragma unroll
    for (int mt = 0; mt < 4; mt++) {
        #pragma unroll
        for (int half = 0; half < 2; half++) {
            int m = m0 + wm * 64 + mt * 16 + g + half * 8;
            if ((MODE >= 2) && m >= cnt) continue;
            #pragma unroll
            for (int nt = 0; nt < 4; nt++) {
                int n = n0 + wn * 32 + nt * 8 + 2 * tig;
                float c0 = acc[mt][nt][half * 2 + 0];
                float c1 = acc[mt][nt][half * 2 + 1];
                if (MODE == 0) {
                    *(float2*)(g_qkv + (size_t)m * QKVN + n) = make_float2(c0, c1);
                } else if (MODE == 1) {
                    float2 r = *(const float2*)(resid + (size_t)m * H + n);
                    *(float2*)(g_x1 + (size_t)m * H + n) =
                        make_float2(c0 + r.x, c1 + r.y);
                } else if (MODE == 2) {
                    *(float2*)(g_act + (size_t)(e * T + m) * F + n) = make_float2(c0, c1);
                } else if (MODE == 3) {
                    float* dst = g_act + (size_t)(e * T + m) * F + n;
                    float2 h3 = *(const float2*)dst;
                    float s0 = 1.f / (1.f + __expf(-c0));
                    float s1 = 1.f / (1.f + __expf(-c1));
                    *(float2*)dst = make_float2(c0 * s0 * h3.x, c1 * s1 * h3.y);
                } else {
                    *(float2*)(g_y + (size_t)(e * T + m) * H + n) = make_float2(c0, c1);
                }
            }
        }
    }
}

__global__ void rope_kernel(const int* __restrict__ pos) {
    int t = blockIdx.x;
    int h = threadIdx.x >> 5, d = threadIdx.x & 31;
    float p = (float)pos[t];
    float inv = powf(10000.f, -(float)d / 32.f);
    float ang = p * inv;
    float c, s;
    sincosf(ang, &s, &c);
    float* base = g_qkv + (size_t)t * QKVN + h * HD;
    float x1 = base[d], x2 = base[d + 32];
    base[d]      = x1 * c - x2 * s;
    base[d + 32] = x2 * c + x1 * s;
}

// ---------------- TF32 tensor-core flash attention (unchanged) -------------
__global__ __launch_bounds__(128) void attn_tc() {
    __shared__ unsigned KVs[64][68];
    __shared__ unsigned Ps[64][68];
    int qt = (int)gridDim.x - 1 - blockIdx.x;
    int h = blockIdx.y;
    int q0 = qt * 64;
    int kvh = h >> 2;
    int tid = threadIdx.x, warp = tid >> 5, lane = tid & 31;
    int g = lane >> 2, tig = lane & 3;
    int wrow = warp * 16;
    int ldr = tid >> 1, ldk = (tid & 1) * 32;

    {
        const float* src = g_qkv + (size_t)(q0 + ldr) * QKVN + h * HD + ldk;
        #pragma unroll
        for (int i = 0; i < 32; i += 4) {
            float4 v = *(const float4*)(src + i);
            KVs[ldr][ldk+i+0] = f2tf(v.x * 0.125f);
            KVs[ldr][ldk+i+1] = f2tf(v.y * 0.125f);
            KVs[ldr][ldk+i+2] = f2tf(v.z * 0.125f);
            KVs[ldr][ldk+i+3] = f2tf(v.w * 0.125f);
        }
    }
    __syncthreads();
    unsigned qf[8][4];
    #pragma unroll
    for (int kk = 0; kk < 8; kk++) {
        qf[kk][0] = KVs[wrow + g][kk * 8 + tig];
        qf[kk][1] = KVs[wrow + g + 8][kk * 8 + tig];
        qf[kk][2] = KVs[wrow + g][kk * 8 + tig + 4];
        qf[kk][3] = KVs[wrow + g + 8][kk * 8 + tig + 4];
    }

    float m_i[2] = {-1e30f, -1e30f};
    float l_i[2] = {0.f, 0.f};
    float O[8][4];
    #pragma unroll
    for (int nt = 0; nt < 8; nt++)
        O[nt][0] = O[nt][1] = O[nt][2] = O[nt][3] = 0.f;

    for (int kt = 0; kt <= qt; kt++) {
        int k0 = kt * 64;
        __syncthreads();
        {
            const float* src = g_qkv + (size_t)(k0 + ldr) * QKVN + 1024 + kvh * HD + ldk;
            #pragma unroll
            for (int i = 0; i < 32; i += 4) {
                float4 v = *(const float4*)(src + i);
                KVs[ldr][ldk+i+0] = f2tf(v.x);
                KVs[ldr][ldk+i+1] = f2tf(v.y);
                KVs[ldr][ldk+i+2] = f2tf(v.z);
                KVs[ldr][ldk+i+3] = f2tf(v.w);
            }
        }
        __syncthreads();

        float S[8][4];
        #pragma unroll
        for (int nt = 0; nt < 8; nt++)
            S[nt][0] = S[nt][1] = S[nt][2] = S[nt][3] = 0.f;
        #pragma unroll
        for (int kk = 0; kk < 8; kk++) {
            #pragma unroll
            for (int nt = 0; nt < 8; nt++) {
                unsigned b[2] = {KVs[nt * 8 + g][kk * 8 + tig],
                                 KVs[nt * 8 + g][kk * 8 + tig + 4]};
                mma_tf32(S[nt], qf[kk], b);
            }
        }

        if (kt == qt) {
            #pragma unroll
            for (int nt = 0; nt < 8; nt++) {
                int colb = nt * 8 + 2 * tig;
                if (colb     > wrow + g)     S[nt][0] = -1e30f;
                if (colb + 1 > wrow + g)     S[nt][1] = -1e30f;
                if (colb     > wrow + g + 8) S[nt][2] = -1e30f;
                if (colb + 1 > wrow + g + 8) S[nt][3] = -1e30f;
            }
        }
        float mx0 = -1e30f, mx1 = -1e30f;
        #pragma unroll
        for (int nt = 0; nt < 8; nt++) {
            mx0 = fmaxf(mx0, fmaxf(S[nt][0], S[nt][1]));
            mx1 = fmaxf(mx1, fmaxf(S[nt][2], S[nt][3]));
        }
        #pragma unroll
        for (int o = 1; o <= 2; o <<= 1) {
            mx0 = fmaxf(mx0, __shfl_xor_sync(0xffffffffu, mx0, o));
            mx1 = fmaxf(mx1, __shfl_xor_sync(0xffffffffu, mx1, o));
        }
        float mn0 = fmaxf(m_i[0], mx0), mn1 = fmaxf(m_i[1], mx1);
        float fac0 = __expf(m_i[0] - mn0), fac1 = __expf(m_i[1] - mn1);
        float rs0 = 0.f, rs1 = 0.f;
        #pragma unroll
        for (int nt = 0; nt < 8; nt++) {
            int colb = nt * 8 + 2 * tig;
            float p00 = __expf(S[nt][0] - mn0);
            float p01 = __expf(S[nt][1] - mn0);
            float p10 = __expf(S[nt][2] - mn1);
            float p11 = __expf(S[nt][3] - mn1);
            rs0 += p00 + p01; rs1 += p10 + p11;
            Ps[wrow + g][colb]     = f2tf(p00);
            Ps[wrow + g][colb + 1] = f2tf(p01);
            Ps[wrow + g + 8][colb]     = f2tf(p10);
            Ps[wrow + g + 8][colb + 1] = f2tf(p11);
        }
        #pragma unroll
        for (int o = 1; o <= 2; o <<= 1) {
            rs0 += __shfl_xor_sync(0xffffffffu, rs0, o);
            rs1 += __shfl_xor_sync(0xffffffffu, rs1, o);
        }
        l_i[0] = l_i[0] * fac0 + rs0;
        l_i[1] = l_i[1] * fac1 + rs1;
        m_i[0] = mn0; m_i[1] = mn1;
        #pragma unroll
        for (int nt = 0; nt < 8; nt++) {
            O[nt][0] *= fac0; O[nt][1] *= fac0;
            O[nt][2] *= fac1; O[nt][3] *= fac1;
        }

        __syncthreads();
        {
            const float* src = g_qkv + (size_t)(k0 + ldr) * QKVN + 1280 + kvh * HD + ldk;
            #pragma unroll
            for (int i = 0; i < 32; i += 4) {
                float4 v = *(const float4*)(src + i);
                KVs[ldk+i+0][ldr] = f2tf(v.x);
                KVs[ldk+i+1][ldr] = f2tf(v.y);
                KVs[ldk+i+2][ldr] = f2tf(v.z);
                KVs[ldk+i+3][ldr] = f2tf(v.w);
            }
        }
        __syncthreads();
        #pragma unroll
        for (int kk = 0; kk < 8; kk++) {
            unsigned af[4] = {Ps[wrow + g][kk * 8 + tig],
                              Ps[wrow + g + 8][kk * 8 + tig],
                              Ps[wrow + g][kk * 8 + tig + 4],
                              Ps[wrow + g + 8][kk * 8 + tig + 4]};
            #pragma unroll
            for (int nt = 0; nt < 8; nt++) {
                unsigned b[2] = {KVs[nt * 8 + g][kk * 8 + tig],
                                 KVs[nt * 8 + g][kk * 8 + tig + 4]};
                mma_tf32(O[nt], af, b);
            }
        }
    }

    float inv0 = 1.f / l_i[0], inv1 = 1.f / l_i[1];
    #pragma unroll
    for (int nt = 0; nt < 8; nt++) {
        int n = h * HD + nt * 8 + 2 * tig;
        *(float2*)(g_attn + (size_t)(q0 + wrow + g) * (NH * HD) + n) =
            make_float2(O[nt][0] * inv0, O[nt][1] * inv0);
        *(float2*)(g_attn + (size_t)(q0 + wrow + g + 8) * (NH * HD) + n) =
            make_float2(O[nt][2] * inv1, O[nt][3] * inv1);
    }
}

__global__ __launch_bounds__(256) void gate_kernel(const float* __restrict__ gate_w) {
    int t = blockIdx.x;
    const float* x = g_xnorm2 + (size_t)t * H;
    int w = threadIdx.x >> 5, lane = threadIdx.x & 31;
    float s = 0.f;
    const float* gw = gate_w + (size_t)w * H;
    for (int i = lane; i < H; i += 32) s += x[i] * gw[i];
    #pragma unroll
    for (int o = 16; o; o >>= 1) s += __shfl_xor_sync(0xffffffffu, s, o);
    __shared__ float logits[NE];
    if (lane == 0) logits[w] = s;
    __syncthreads();
    if (threadIdx.x == 0) {
        float mx = logits[0];
        #pragma unroll
        for (int e = 1; e < NE; e++) mx = fmaxf(mx, logits[e]);
        float p[NE];
        #pragma unroll
        for (int e = 0; e < NE; e++) p[e] = __expf(logits[e] - mx);
        int i1 = 0;
        #pragma unroll
        for (int e = 1; e < NE; e++) if (p[e] > p[i1]) i1 = e;
        int i2 = (i1 == 0) ? 1 : 0;
        #pragma unroll
        for (int e = 0; e < NE; e++) if (e != i1 && p[e] > p[i2]) i2 = e;
        float inv = 1.f / (p[i1] + p[i2]);
        int s0 = atomicAdd(&g_cnt[i1], 1);
        g_ptok[i1 * T + s0] = t;
        g_slot[2 * t + 0] = i1 * T + s0;
        g_gatew[2 * t + 0] = p[i1] * inv;
        int s1 = atomicAdd(&g_cnt[i2], 1);
        g_ptok[i2 * T + s1] = t;
        g_slot[2 * t + 1] = i2 * T + s1;
        g_gatew[2 * t + 1] = p[i2] * inv;
    }
}

// x = x1 + g0*y0 + g1*y1; rmsnorm(x) -> out[0..T*H); x -> out[T*H..) if room.
__global__ __launch_bounds__(256) void combine_kernel(
    const float* __restrict__ w_next, float* __restrict__ out, int write_x)
{
    __shared__ float xs[H];
    int t = blockIdx.x;
    int s0 = g_slot[2 * t + 0], s1 = g_slot[2 * t + 1];
    float g0 = g_gatew[2 * t + 0], g1 = g_gatew[2 * t + 1];
    float ss = 0.f;
    for (int i = threadIdx.x; i < H; i += 256) {
        float v = g_x1[(size_t)t * H + i]
                + g0 * g_y[(size_t)s0 * H + i]
                + g1 * g_y[(size_t)s1 * H + i];
        xs[i] = v;
        if (write_x) out[(size_t)T * H + (size_t)t * H + i] = v;
        ss += v * v;
    }
    float tot = block_sum_256(ss);
    float scale = rsqrtf(tot / (float)H + EPS);
    __syncthreads();
    for (int i = threadIdx.x; i < H; i += 256)
        out[(size_t)t * H + i] = xs[i] * scale * w_next[i];
}

// ------------------------------------------------------------------- launch
extern "C" void kernel_launch(void* const* d_in, const int* in_sizes, int n_in,
                              void* d_out, int out_size)
{
    const int*   positions = nullptr;
    const float* hidden = nullptr;
    const float* w_qkv = nullptr;
    const float* w_o = nullptr;
    const float* gate_w = nullptr;
    const float* norms[3] = {nullptr, nullptr, nullptr};
    const float* big[3]   = {nullptr, nullptr, nullptr};
    int nn = 0, nb = 0;
    for (int i = 0; i < n_in; i++) {
        switch (in_sizes[i]) {
            case 2048:     positions = (const int*)d_in[i];   break;
            case 2097152:  hidden    = (const float*)d_in[i]; break;
            case 1572864:  w_qkv     = (const float*)d_in[i]; break;
            case 1048576:  w_o       = (const float*)d_in[i]; break;
            case 8192:     gate_w    = (const float*)d_in[i]; break;
            case 1024:     if (nn < 3) norms[nn++] = (const float*)d_in[i]; break;
            case 16777216: if (nb < 3) big[nb++]   = (const float*)d_in[i]; break;
            default: break;
        }
    }
    const float* norm_in   = norms[0];
    const float* norm_post = norms[1];
    const float* norm_next = norms[2];
    const float* w1 = big[0];
    const float* w2 = big[1];
    const float* w3 = big[2];
    float* out = (float*)d_out;

    int write_x = (out_size == 2 * T * H || out_size == 2 * T * H * 4) ? 1 : 0;

    // one-shot weight conversions (graph-replayed; deterministic)
    cvt_bf16_kernel<0><<<512, 256>>>((const float4*)w_qkv, QKVN * H / 4);
    cvt_bf16_kernel<1><<<512, 256>>>((const float4*)w_o, H * NH * HD / 4);
    cvt_bf16_kernel<2><<<2048, 256>>>((const float4*)w1, NE * F * H / 4);
    cvt_bf16_kernel<3><<<2048, 256>>>((const float4*)w2, NE * H * F / 4);
    cvt_bf16_kernel<4><<<2048, 256>>>((const float4*)w3, NE * F * H / 4);

    zero_cnt_kernel<<<1, 32>>>();
    rmsnorm_kernel<0><<<T, 256>>>(hidden, norm_in);
    gemm_tc<0><<<dim3(QKVN / 128, T / 128), 256>>>(nullptr);
    rope_kernel<<<T, (NH + NKV) * 32>>>(positions);
    attn_tc<<<dim3(T / 64, NH), 128>>>();
    gemm_tc<1><<<dim3(H / 128, T / 128), 256>>>(hidden);
    rmsnorm_kernel<1><<<T, 256>>>(nullptr, norm_post);
    gate_kernel<<<T, 256>>>(gate_w);
    gemm_tc<2><<<dim3(F / 128, T / 128, NE), 256>>>(nullptr);
    gemm_tc<3><<<dim3(F / 128, T / 128, NE), 256>>>(nullptr);
    gemm_tc<4><<<dim3(H / 128, T / 128, NE), 256>>>(nullptr);
    combine_kernel<<<T, 256>>>(norm_next, out, write_x);
}